// round 14
// baseline (speedup 1.0000x reference)
#include <cuda_runtime.h>
#include <cuda_fp16.h>
#include <cstdint>

// ---------------------------------------------------------------------------
// VQVAE forward on sm_103 (ldmatrix + mma.sync fp16 + cp.async).
//   Balanced half-tile warp split: every warp owns 32 rows (2 m16 blocks);
//   group0 (w<4): z tiles 0-6 + dot tile 15;  group1: z tiles 7-12 + dots 13-14.
//   B-fragment ldsm traffic -44% vs all-warps-all-tiles; per-SMSP load even.
//   A scaled 2^8, B scaled 2^10 fp16 split; z = hh only; dots = hh+lh+hl.
//   Double-buffered smem; B cp.async'd one chunk ahead; x reg-prefetched.
//   argmin/loss: quad shfl reduce + smem combine across groups.
//   x_recon: fused gather from precomputed 21x1024 table, streaming stores.
// ---------------------------------------------------------------------------

#define NCODES 21
#define LDIM   100
#define IDIM   1024
#define NPAD   128
#define CTA_M  128
#define KC     64
#define NCHUNK (IDIM / KC)

#define ASCALE 256.0f                 // 2^8
#define BSCALE 1024.0f                // 2^10
#define INVS   3.814697265625e-06f    // 2^-18

__device__ __half g_Bh[NPAD * IDIM];
__device__ __half g_Bl[NPAD * IDIM];
__device__ float  g_recon[NCODES * IDIM];
__device__ float  g_ck[NCODES];            // ||c_k||^2 - 2 b.c_k
__device__ double g_loss;

__device__ __forceinline__ uint32_t smem_u32(const void* p) {
    uint32_t a;
    asm("{ .reg .u64 t; cvta.to.shared.u64 t, %1; cvt.u32.u64 %0, t; }"
        : "=r"(a) : "l"(p));
    return a;
}
__device__ __forceinline__ uint32_t pack_f16x2(float a, float b) {
    uint32_t r;   // low 16 = a, high 16 = b
    asm("cvt.rn.f16x2.f32 %0, %1, %2;" : "=r"(r) : "f"(b), "f"(a));
    return r;
}
__device__ __forceinline__ float2 unpack_h2(uint32_t p) {
    __half2 h = *reinterpret_cast<__half2*>(&p);
    return __half22float2(h);
}
__device__ __forceinline__ uint32_t swz(uint32_t o) { return o ^ ((o >> 3) & 0x70u); }

__device__ __forceinline__ void ldsm_x4(uint32_t* r, uint32_t addr) {
    asm volatile("ldmatrix.sync.aligned.m8n8.x4.shared.b16 {%0,%1,%2,%3}, [%4];"
                 : "=r"(r[0]), "=r"(r[1]), "=r"(r[2]), "=r"(r[3]) : "r"(addr));
}
__device__ __forceinline__ void ldsm_x2(uint32_t* r, uint32_t addr) {
    asm volatile("ldmatrix.sync.aligned.m8n8.x2.shared.b16 {%0,%1}, [%2];"
                 : "=r"(r[0]), "=r"(r[1]) : "r"(addr));
}
__device__ __forceinline__ void mma_f16(float* d, const uint32_t* a, const uint32_t* b) {
    asm volatile("mma.sync.aligned.m16n8k16.row.col.f32.f16.f16.f32 "
                 "{%0,%1,%2,%3}, {%4,%5,%6,%7}, {%8,%9}, {%0,%1,%2,%3};"
                 : "+f"(d[0]), "+f"(d[1]), "+f"(d[2]), "+f"(d[3])
                 : "r"(a[0]), "r"(a[1]), "r"(a[2]), "r"(a[3]),
                   "r"(b[0]), "r"(b[1]));
}
__device__ __forceinline__ void stcs4(float* p, float4 v) {
    asm volatile("st.global.cs.v4.f32 [%0], {%1,%2,%3,%4};"
                 :: "l"(p), "f"(v.x), "f"(v.y), "f"(v.z), "f"(v.w) : "memory");
}
#define CP_ASYNC16(dst, src) \
    asm volatile("cp.async.cg.shared.global [%0], [%1], 16;" \
                 :: "r"(dst), "l"(src) : "memory")
#define CP_COMMIT() asm volatile("cp.async.commit_group;" ::: "memory")
#define CP_WAIT0()  asm volatile("cp.async.wait_group 0;" ::: "memory")

// ---------------- smem layout: two 52KB buffers + consts ---------------------
#define BUF_STRIDE 53248
#define OFF_AH   0
#define OFF_AL   16384
#define OFF_BH   32768
#define OFF_BL   49152          // 32 rows (96..127) -> 4 KB
#define OFF_BES  106496
#define OFF_CK   107008
#define OFF_SIDX 107136
#define OFF_ZZA  107648
#define OFF_BDA  108160
#define OFF_BKA  108672
#define OFF_LOSS 109184
#define SMEM_BYTES (109200 + 128)

// ---------------------------------------------------------------------------
// K0: setup — extended B (W_enc rows 0..99, cb@W_enc rows 104..124, rest 0),
//             recon table, ck consts, loss reset
// ---------------------------------------------------------------------------
__global__ void vq_setup_kernel(const float* __restrict__ W_enc,
                                const float* __restrict__ b_enc,
                                const float* __restrict__ codebook,
                                const float* __restrict__ W_dec,
                                const float* __restrict__ b_dec) {
    int g = blockIdx.x * 256 + threadIdx.x;            // 0 .. 131071
    {
        int n = g >> 10, k = g & 1023;
        float w = 0.f;
        if (n < LDIM) {
            w = W_enc[n * IDIM + k];
        } else if (n >= 104 && n < 104 + NCODES) {
            const float* cb = codebook + (n - 104) * LDIM;
#pragma unroll 20
            for (int j = 0; j < LDIM; ++j) w += cb[j] * W_enc[j * IDIM + k];
        }
        float ws = w * BSCALE;
        __half h = __float2half_rn(ws);
        g_Bh[g] = h;
        g_Bl[g] = __float2half_rn(ws - __half2float(h));
    }
    if (g < NCODES * IDIM) {
        int k = g >> 10, d = g & 1023;
        const float4* c4 = (const float4*)(codebook + k * LDIM);
        const float4* w4 = (const float4*)(W_dec + (size_t)d * LDIM);
        float s = b_dec[d];
#pragma unroll
        for (int j = 0; j < LDIM / 4; ++j) {
            float4 a = c4[j], b = w4[j];
            s += a.x * b.x + a.y * b.y + a.z * b.z + a.w * b.w;
        }
        g_recon[g] = s;
    }
    if (g < NCODES) {
        const float* c = codebook + g * LDIM;
        float cn = 0.f, bk = 0.f;
#pragma unroll 10
        for (int j = 0; j < LDIM; ++j) { cn += c[j] * c[j]; bk += b_enc[j] * c[j]; }
        g_ck[g] = cn - 2.f * bk;
    }
    if (g == 0) g_loss = 0.0;
}

// ---------------------------------------------------------------------------
// K1: main — HMMA scaled-fp16-split GEMM + fused argmin/loss/recon
// ---------------------------------------------------------------------------
extern __shared__ __align__(16) char dsm_raw[];

__global__ __launch_bounds__(256, 2)
void vq_main_kernel(const float* __restrict__ x,
                    const float* __restrict__ b_enc,
                    float* __restrict__ out_recon,
                    float* __restrict__ out_idx) {
    const int t = threadIdx.x;
    const int w = t >> 5, L = t & 31;
    const int row0 = blockIdx.x * CTA_M;

    uint32_t raw  = smem_u32(dsm_raw);
    uint32_t base = (raw + 127u) & ~127u;
    char* sm = dsm_raw + (base - raw);

    float* bes   = (float*)(sm + OFF_BES);
    float* cks   = (float*)(sm + OFF_CK);
    int*   sidx  = (int*)  (sm + OFF_SIDX);
    float* zzA   = (float*)(sm + OFF_ZZA);
    float* bdA   = (float*)(sm + OFF_BDA);
    int*   bkA   = (int*)  (sm + OFF_BKA);
    float* sloss = (float*)(sm + OFF_LOSS);

    if (t < LDIM)   bes[t] = b_enc[t];
    if (t < NCODES) cks[t] = g_ck[t];
    if (t == 0)     *sloss = 0.f;

    const bool g0 = (w < 4);
    const int  wl = w & 3;             // rows wl*32 .. wl*32+31

    float acc[2][8][4];                // [m-block][slot][frag]
#pragma unroll
    for (int b = 0; b < 2; ++b)
#pragma unroll
        for (int j = 0; j < 8; ++j)
#pragma unroll
            for (int e = 0; e < 4; ++e) acc[b][j][e] = 0.f;

    const uint32_t mask  = (uint32_t)(L & 7) << 4;
    const uint32_t lowA0 = ((uint32_t)(L & 7) << 7) + ((uint32_t)(L >> 4) << 4);
    const uint32_t lowB4 = ((uint32_t)(L & 7) << 7) + ((uint32_t)((L >> 3) & 1) << 4)
                         + ((uint32_t)(L >> 4) << 10);
    const uint32_t aRow  = ((uint32_t)(wl * 4 + ((L >> 3) & 1))) << 10;

    // per-thread source coords (conversion covers all 128 rows, all warps)
    const int xr = (t >> 4);
    const int xc = (t & 15) * 4;

    // staging coords (B)
    const int sb_n  = t >> 3;
    const int sb_k8 = (t & 7) * 8;

    auto stageB = [&](int ch, int buf) {
        const int kc = ch * KC;
        uint32_t bOff = base + buf * BUF_STRIDE;
#pragma unroll
        for (int it = 0; it < 4; ++it) {
            int n = it * 32 + sb_n;
            uint32_t dst = bOff + OFF_BH + swz((uint32_t)(n * 128 + sb_k8 * 2));
            CP_ASYNC16(dst, (const void*)(g_Bh + (size_t)n * IDIM + kc + sb_k8));
        }
        {
            uint32_t dst = bOff + OFF_BL + swz((uint32_t)(sb_n * 128 + sb_k8 * 2));
            CP_ASYNC16(dst, (const void*)(g_Bl + (size_t)(96 + sb_n) * IDIM + kc + sb_k8));
        }
        CP_COMMIT();
    };
    auto convertA = [&](const float4* xv, int buf) {
        char* Ah = sm + buf * BUF_STRIDE + OFF_AH;
        char* Al = sm + buf * BUF_STRIDE + OFF_AL;
#pragma unroll
        for (int it = 0; it < 8; ++it) {
            float4 v = xv[it];
            int row = it * 16 + xr;
            float sx = v.x * ASCALE, sy = v.y * ASCALE;
            float sz = v.z * ASCALE, sw = v.w * ASCALE;
            uint32_t h01 = pack_f16x2(sx, sy);
            uint32_t h23 = pack_f16x2(sz, sw);
            float2 b01 = unpack_h2(h01), b23 = unpack_h2(h23);
            uint32_t l01 = pack_f16x2(sx - b01.x, sy - b01.y);
            uint32_t l23 = pack_f16x2(sz - b23.x, sw - b23.y);
            uint32_t off = swz((uint32_t)(row * 128 + xc * 2));
            *(uint2*)(Ah + off) = make_uint2(h01, h23);
            *(uint2*)(Al + off) = make_uint2(l01, l23);
        }
    };

    // ---- prologue: chunk 0
    float4 xv[8];
#pragma unroll
    for (int it = 0; it < 8; ++it)
        xv[it] = *(const float4*)(x + (size_t)(row0 + it * 16 + xr) * IDIM + xc);
    stageB(0, 0);
    convertA(xv, 0);
    CP_WAIT0();
    __syncthreads();

    for (int ch = 0; ch < NCHUNK; ++ch) {
        const int buf  = ch & 1;
        const int nbuf = buf ^ 1;
        const uint32_t bufAdd = (uint32_t)(buf * BUF_STRIDE);
        const uint32_t AhB = base + bufAdd + OFF_AH + aRow;
        const uint32_t AlB = base + bufAdd + OFF_AL + aRow;
        const uint32_t BhB = base + bufAdd + OFF_BH;
        const uint32_t BlB = base + bufAdd + OFF_BL - (12 << 10);   // tiles >=12

        const bool more = (ch + 1 < NCHUNK);
        if (more) {
            const float* xn = x + (ch + 1) * KC + xc;
#pragma unroll
            for (int it = 0; it < 8; ++it)
                xv[it] = *(const float4*)(xn + (size_t)(row0 + it * 16 + xr) * IDIM);
            stageB(ch + 1, nbuf);
        }

#pragma unroll
        for (int ks = 0; ks < 4; ++ks) {
            const uint32_t aoff = (lowA0 + (ks << 5)) ^ mask;
            const uint32_t boff = (lowB4 + (ks << 5)) ^ mask;
            uint32_t ah0[4], ah1[4], al0[4], al1[4];
            ldsm_x4(ah0, AhB + aoff);
            ldsm_x4(ah1, AhB + (2 << 10) + aoff);
            ldsm_x4(al0, AlB + aoff);
            ldsm_x4(al1, AlB + (2 << 10) + aoff);
            if (g0) {
                // z tiles 0..5 (pairs) -> slots 0..5
#pragma unroll
                for (int jp = 0; jp < 6; jp += 2) {
                    uint32_t bh[4];
                    ldsm_x4(bh, BhB + boff + (jp << 10));
                    mma_f16(acc[0][jp],     ah0, bh);
                    mma_f16(acc[0][jp + 1], ah0, bh + 2);
                    mma_f16(acc[1][jp],     ah1, bh);
                    mma_f16(acc[1][jp + 1], ah1, bh + 2);
                }
                // z tile 6 -> slot 6
                {
                    uint32_t b6[2];
                    ldsm_x2(b6, BhB + boff + (6 << 10));
                    mma_f16(acc[0][6], ah0, b6);
                    mma_f16(acc[1][6], ah1, b6);
                }
                // dot tile 15 (k 16..20) -> slot 7: hh+lh+hl
                {
                    uint32_t bh[2], bl[2];
                    ldsm_x2(bh, BhB + boff + (15 << 10));
                    ldsm_x2(bl, BlB + boff + (15 << 10));
                    mma_f16(acc[0][7], ah0, bh);
                    mma_f16(acc[0][7], al0, bh);
                    mma_f16(acc[0][7], ah0, bl);
                    mma_f16(acc[1][7], ah1, bh);
                    mma_f16(acc[1][7], al1, bh);
                    mma_f16(acc[1][7], ah1, bl);
                }
            } else {
                // z tiles 7..12 (pairs) -> slots 0..5
#pragma unroll
                for (int jp = 0; jp < 6; jp += 2) {
                    uint32_t bh[4];
                    ldsm_x4(bh, BhB + boff + ((7 + jp) << 10));
                    mma_f16(acc[0][jp],     ah0, bh);
                    mma_f16(acc[0][jp + 1], ah0, bh + 2);
                    mma_f16(acc[1][jp],     ah1, bh);
                    mma_f16(acc[1][jp + 1], ah1, bh + 2);
                }
                // dot tiles 13,14 (k 0..15) -> slots 6,7: hh+lh+hl
                {
                    uint32_t bh[4], bl[4];
                    ldsm_x4(bh, BhB + boff + (13 << 10));
                    ldsm_x4(bl, BlB + boff + (13 << 10));
                    mma_f16(acc[0][6], ah0, bh);
                    mma_f16(acc[0][6], al0, bh);
                    mma_f16(acc[0][6], ah0, bl);
                    mma_f16(acc[1][6], ah1, bh);
                    mma_f16(acc[1][6], al1, bh);
                    mma_f16(acc[1][6], ah1, bl);
                    mma_f16(acc[0][7], ah0, bh + 2);
                    mma_f16(acc[0][7], al0, bh + 2);
                    mma_f16(acc[0][7], ah0, bl + 2);
                    mma_f16(acc[1][7], ah1, bh + 2);
                    mma_f16(acc[1][7], al1, bh + 2);
                    mma_f16(acc[1][7], ah1, bl + 2);
                }
            }
        }

        if (more) {
            convertA(xv, nbuf);
            CP_WAIT0();
            __syncthreads();
        }
    }

    // ---- epilogue. Thread owns rows wl*32 + mb*16 + q (+8), c0 = L&3, q = L>>2.
    const int c0 = L & 3, q = L >> 2;
    float zz[2][2] = {{0.f, 0.f}, {0.f, 0.f}};
    float bd[2][2] = {{3.4e38f, 3.4e38f}, {3.4e38f, 3.4e38f}};
    int   bk[2][2] = {{NCODES, NCODES}, {NCODES, NCODES}};

    if (g0) {
        // zz over cols 0..55 (slots 0..6)
#pragma unroll
        for (int j = 0; j < 7; ++j) {
#pragma unroll
            for (int e = 0; e < 2; ++e) {
                int col = 8 * j + 2 * c0 + e;
                float b = bes[col];
                float z;
                z = fmaf(acc[0][j][e],     INVS, b);  zz[0][0] += z * z;
                z = fmaf(acc[0][j][e + 2], INVS, b);  zz[0][1] += z * z;
                z = fmaf(acc[1][j][e],     INVS, b);  zz[1][0] += z * z;
                z = fmaf(acc[1][j][e + 2], INVS, b);  zz[1][1] += z * z;
            }
        }
        // dots k 16..20 (slot 7)
#pragma unroll
        for (int e = 0; e < 2; ++e) {
            int k = 16 + 2 * c0 + e;
            if (k < NCODES) {
                float ckv = cks[k];
                float s;
                s = fmaf(acc[0][7][e],     -2.f * INVS, ckv);
                if (s < bd[0][0]) { bd[0][0] = s; bk[0][0] = k; }
                s = fmaf(acc[0][7][e + 2], -2.f * INVS, ckv);
                if (s < bd[0][1]) { bd[0][1] = s; bk[0][1] = k; }
                s = fmaf(acc[1][7][e],     -2.f * INVS, ckv);
                if (s < bd[1][0]) { bd[1][0] = s; bk[1][0] = k; }
                s = fmaf(acc[1][7][e + 2], -2.f * INVS, ckv);
                if (s < bd[1][1]) { bd[1][1] = s; bk[1][1] = k; }
            }
        }
    } else {
        // zz over cols 56..99 (slots 0..5; slot 5 guarded)
#pragma unroll
        for (int j = 0; j < 6; ++j) {
#pragma unroll
            for (int e = 0; e < 2; ++e) {
                int col = 56 + 8 * j + 2 * c0 + e;
                if (col < LDIM) {
                    float b = bes[col];
                    float z;
                    z = fmaf(acc[0][j][e],     INVS, b);  zz[0][0] += z * z;
                    z = fmaf(acc[0][j][e + 2], INVS, b);  zz[0][1] += z * z;
                    z = fmaf(acc[1][j][e],     INVS, b);  zz[1][0] += z * z;
                    z = fmaf(acc[1][j][e + 2], INVS, b);  zz[1][1] += z * z;
                }
            }
        }
        // dots k 0..15 (slots 6,7)
#pragma unroll
        for (int j = 6; j < 8; ++j) {
#pragma unroll
            for (int e = 0; e < 2; ++e) {
                int k = 8 * (j - 6) + 2 * c0 + e;
                float ckv = cks[k];
                float s;
                s = fmaf(acc[0][j][e],     -2.f * INVS, ckv);
                if (s < bd[0][0]) { bd[0][0] = s; bk[0][0] = k; }
                s = fmaf(acc[0][j][e + 2], -2.f * INVS, ckv);
                if (s < bd[0][1]) { bd[0][1] = s; bk[0][1] = k; }
                s = fmaf(acc[1][j][e],     -2.f * INVS, ckv);
                if (s < bd[1][0]) { bd[1][0] = s; bk[1][0] = k; }
                s = fmaf(acc[1][j][e + 2], -2.f * INVS, ckv);
                if (s < bd[1][1]) { bd[1][1] = s; bk[1][1] = k; }
            }
        }
    }
    // quad reduce (zz sum; bd/bk min, smaller k on ties)
#pragma unroll
    for (int off = 1; off < 4; off <<= 1) {
#pragma unroll
        for (int b = 0; b < 2; ++b)
#pragma unroll
            for (int h = 0; h < 2; ++h) {
                zz[b][h] += __shfl_xor_sync(0xffffffffu, zz[b][h], off);
                float od = __shfl_xor_sync(0xffffffffu, bd[b][h], off);
                int   ok = __shfl_xor_sync(0xffffffffu, bk[b][h], off);
                if (od < bd[b][h] || (od == bd[b][h] && ok < bk[b][h])) {
                    bd[b][h] = od; bk[b][h] = ok;
                }
            }
    }
    __syncthreads();              // MMA/ldsm done; smem buffers reusable
    if (g0 && c0 == 0) {
#pragma unroll
        for (int b = 0; b < 2; ++b)
#pragma unroll
            for (int h = 0; h < 2; ++h) {
                int r = wl * 32 + b * 16 + h * 8 + q;
                zzA[r] = zz[b][h];
                bdA[r] = bd[b][h];
                bkA[r] = bk[b][h];
            }
    }
    __syncthreads();
    if (!g0 && c0 == 0) {
        float lsum = 0.f;
#pragma unroll
        for (int b = 0; b < 2; ++b)
#pragma unroll
            for (int h = 0; h < 2; ++h) {
                int r = wl * 32 + b * 16 + h * 8 + q;
                float bdv = bd[b][h];  int bkv = bk[b][h];
                if (bdA[r] < bdv) { bdv = bdA[r]; bkv = bkA[r]; }  // ties -> group1 (smaller k)
                float zzt = zz[b][h] + zzA[r];
                sidx[r] = bkv;
                out_idx[row0 + r] = (float)bkv;
                lsum += zzt + bdv;
            }
        atomicAdd(sloss, lsum);
    }
    __syncthreads();
    if (t == 0) atomicAdd(&g_loss, (double)*sloss);

    // ---- fused recon gather (table L2-resident; streaming stores)
#pragma unroll 4
    for (int r = 0; r < CTA_M; ++r) {
        int k = sidx[r];
        float4 v = *(const float4*)(g_recon + (size_t)k * IDIM + t * 4);
        stcs4(out_recon + (size_t)(row0 + r) * IDIM + t * 4, v);
    }
}

// ---------------------------------------------------------------------------
// K2: finalize loss
// ---------------------------------------------------------------------------
__global__ void vq_fin_kernel(float* __restrict__ out_loss, int M) {
    out_loss[0] = (float)(1.1 * g_loss / ((double)M * (double)LDIM));
}

extern "C" void kernel_launch(void* const* d_in, const int* in_sizes, int n_in,
                              void* d_out, int out_size) {
    const float* x        = (const float*)d_in[0];
    const float* W_enc    = (const float*)d_in[1];
    const float* b_enc    = (const float*)d_in[2];
    const float* codebook = (const float*)d_in[3];
    const float* W_dec    = (const float*)d_in[4];
    const float* b_dec    = (const float*)d_in[5];
    float* out = (float*)d_out;

    const int M = in_sizes[0] / IDIM;           // 65536
    float* out_recon = out;
    float* out_loss  = out + (size_t)M * IDIM;
    float* out_idx   = out_loss + 1;

    cudaFuncSetAttribute(vq_main_kernel,
                         cudaFuncAttributeMaxDynamicSharedMemorySize, SMEM_BYTES);

    vq_setup_kernel<<<(NPAD * IDIM) / 256, 256>>>(W_enc, b_enc, codebook, W_dec, b_dec);
    vq_main_kernel<<<M / CTA_M, 256, SMEM_BYTES>>>(x, b_enc, out_recon, out_idx);
    vq_fin_kernel<<<1, 1>>>(out_loss, M);
}